// round 2
// baseline (speedup 1.0000x reference)
#include <cuda_runtime.h>
#include <math.h>

#define NDIM 512
#define BATCH 256
#define SPLIT 8                       // chunks per batch row
#define CHUNK_F4 (NDIM * NDIM / 4 / SPLIT)   // 8192 float4 per chunk
#define ITERS (CHUNK_F4 / 512)               // 16 float4 per thread

// Scratch: projected weight vectors and per-chunk partial sums.
__device__ float  g_u[NDIM];
__device__ float  g_v[NDIM];
__device__ double g_part[BATCH * SPLIT];

// ---------------------------------------------------------------------------
// Kernel A: block k computes u[k] = sum_i basis[i,k] wh[i], same for v.
// Integer-exact mod-2pi reduction of the cos argument.
// ---------------------------------------------------------------------------
__global__ __launch_bounds__(256) void proj_kernel(const float* __restrict__ wh,
                                                   const float* __restrict__ wv) {
    const int k = blockIdx.x;
    const int t = threadIdx.x;
    const int twoK1 = 2 * k + 1;
    const float step = 3.14159265358979323846f / 1024.0f;

    float su = 0.0f, sv = 0.0f;
#pragma unroll
    for (int r = 0; r < 2; ++r) {
        const int i = t + r * 256;
        const int m = (twoK1 * i) & 2047;
        const float c = cosf((float)m * step);
        const float cu = (i == 0) ? 0.04419417382415922f : 0.0625f;
        const float bc = cu * c;
        su = fmaf(bc, wh[i], su);
        sv = fmaf(bc, wv[i], sv);
    }
#pragma unroll
    for (int o = 16; o; o >>= 1) {
        su += __shfl_down_sync(0xffffffffu, su, o);
        sv += __shfl_down_sync(0xffffffffu, sv, o);
    }
    __shared__ float s_u[8];
    __shared__ float s_v[8];
    if ((t & 31) == 0) { s_u[t >> 5] = su; s_v[t >> 5] = sv; }
    __syncthreads();
    if (t < 32) {
        float a = (t < 8) ? s_u[t] : 0.0f;
        float b = (t < 8) ? s_v[t] : 0.0f;
#pragma unroll
        for (int o = 4; o; o >>= 1) {
            a += __shfl_down_sync(0xffffffffu, a, o);
            b += __shfl_down_sync(0xffffffffu, b, o);
        }
        if (t == 0) { g_u[k] = a; g_v[k] = b; }
    }
}

// ---------------------------------------------------------------------------
// Kernel B: grid = BATCH*SPLIT. Block (b, s) streams rows k in
// [s*64, (s+1)*64) of X_b (contiguous 128 KB) and writes a double partial.
// Column slice l = (4t)&511 is loop-invariant -> v4 loaded once from shared.
// ---------------------------------------------------------------------------
__global__ __launch_bounds__(512) void dot_kernel(const float* __restrict__ x) {
    __shared__ __align__(16) float su[NDIM / SPLIT];  // 64 u-values this chunk needs
    __shared__ __align__(16) float sv[NDIM];
    const int t = threadIdx.x;
    const int b = blockIdx.x >> 3;        // batch row
    const int s = blockIdx.x & (SPLIT - 1);

    sv[t] = g_v[t];
    if (t < NDIM / SPLIT) su[t] = g_u[s * (NDIM / SPLIT) + t];
    __syncthreads();

    const float4* __restrict__ xr = reinterpret_cast<const float4*>(
        x + (size_t)b * NDIM * NDIM + (size_t)s * (NDIM * NDIM / SPLIT));

    const int l  = (4 * t) & 511;
    const int k0 = (4 * t) >> 9;          // 0..3 within this chunk's rows
    const float4 v4 = *reinterpret_cast<const float4*>(&sv[l]);

    double acc = 0.0;
#pragma unroll
    for (int i = 0; i < ITERS; ++i) {
        const float4 xx = __ldcs(&xr[t + 512 * i]);
        const float uk = su[k0 + 4 * i];
        float d = xx.x * v4.x;
        d = fmaf(xx.y, v4.y, d);
        d = fmaf(xx.z, v4.z, d);
        d = fmaf(xx.w, v4.w, d);
        acc += (double)(uk * d);
    }

#pragma unroll
    for (int o = 16; o; o >>= 1)
        acc += __shfl_down_sync(0xffffffffu, acc, o);

    __shared__ double wsum[16];
    if ((t & 31) == 0) wsum[t >> 5] = acc;
    __syncthreads();
    if (t < 32) {
        double v = (t < 16) ? wsum[t] : 0.0;
#pragma unroll
        for (int o = 8; o; o >>= 1)
            v += __shfl_down_sync(0xffffffffu, v, o);
        if (t == 0) g_part[blockIdx.x] = v;
    }
}

// ---------------------------------------------------------------------------
// Kernel C: reduce SPLIT partials per row, sigmoid, write out.
// ---------------------------------------------------------------------------
__global__ __launch_bounds__(BATCH) void finish_kernel(const float* __restrict__ bias,
                                                       float* __restrict__ out) {
    const int b = threadIdx.x;
    double s = 0.0;
#pragma unroll
    for (int i = 0; i < SPLIT; ++i) s += g_part[b * SPLIT + i];
    const float val = (float)s + bias[0];
    out[b] = 1.0f / (1.0f + expf(-val));
}

extern "C" void kernel_launch(void* const* d_in, const int* in_sizes, int n_in,
                              void* d_out, int out_size) {
    const float* x    = (const float*)d_in[0];
    const float* wh   = (const float*)d_in[1];
    const float* wv   = (const float*)d_in[2];
    const float* bias = (const float*)d_in[3];
    float* out = (float*)d_out;

    proj_kernel<<<NDIM, 256>>>(wh, wv);
    dot_kernel<<<BATCH * SPLIT, 512>>>(x);
    finish_kernel<<<1, BATCH>>>(bias, out);
}

// round 3
// speedup vs baseline: 1.0061x; 1.0061x over previous
#include <cuda_runtime.h>
#include <math.h>

#define NDIM 512
#define BATCH 256
#define SPLIT 8                              // chunks per batch row
#define ITERS (NDIM * NDIM / 4 / SPLIT / 512)  // 16 float4 per thread

__device__ float  g_u[NDIM];
__device__ float  g_v[NDIM];
__device__ double g_part[BATCH * SPLIT];
__device__ int    g_cnt[BATCH];              // zero-init; self-resetting per launch

// ---------------------------------------------------------------------------
// Kernel A: block k computes u[k] = sum_i cu[i] cos((2k+1)i*pi/1024) wh[i],
// same for v. Integer-exact mod-2pi reduction, folded into [0, pi] so
// __cosf (MUFU) runs at max accuracy. 2 MUFU ops/thread instead of ~60
// FMA-pipe ops for the libm cosf slow path.
// ---------------------------------------------------------------------------
__global__ __launch_bounds__(256) void proj_kernel(const float* __restrict__ wh,
                                                   const float* __restrict__ wv) {
    const int k = blockIdx.x;
    const int t = threadIdx.x;
    const int twoK1 = 2 * k + 1;
    const float step = 3.14159265358979323846f / 1024.0f;

    float su = 0.0f, sv = 0.0f;
#pragma unroll
    for (int r = 0; r < 2; ++r) {
        const int i = t + r * 256;
        int m = (twoK1 * i) & 2047;            // exact mod 2pi (units of pi/1024)
        m = (m > 1024) ? (2048 - m) : m;       // fold: cos(2pi - x) = cos(x)
        const float c = __cosf((float)m * step);   // |arg| <= pi
        const float cu = (i == 0) ? 0.04419417382415922f : 0.0625f;
        const float bc = cu * c;
        su = fmaf(bc, wh[i], su);
        sv = fmaf(bc, wv[i], sv);
    }
#pragma unroll
    for (int o = 16; o; o >>= 1) {
        su += __shfl_down_sync(0xffffffffu, su, o);
        sv += __shfl_down_sync(0xffffffffu, sv, o);
    }
    __shared__ float s_u[8];
    __shared__ float s_v[8];
    if ((t & 31) == 0) { s_u[t >> 5] = su; s_v[t >> 5] = sv; }
    __syncthreads();
    if (t < 32) {
        float a = (t < 8) ? s_u[t] : 0.0f;
        float b = (t < 8) ? s_v[t] : 0.0f;
#pragma unroll
        for (int o = 4; o; o >>= 1) {
            a += __shfl_down_sync(0xffffffffu, a, o);
            b += __shfl_down_sync(0xffffffffu, b, o);
        }
        if (t == 0) { g_u[k] = a; g_v[k] = b; }
    }
}

// ---------------------------------------------------------------------------
// Kernel B: grid = BATCH*SPLIT. Block (b, s) streams rows [s*64, s*64+64) of
// X_b (contiguous 128 KB) with __ldcs float4 loads; double partial per block.
// Last block of each row (atomic-counter elect) sums the 8 partials in fixed
// index order (bitwise deterministic), applies sigmoid, writes out, and
// resets the counter for graph replay.
// ---------------------------------------------------------------------------
__global__ __launch_bounds__(512) void dot_kernel(const float* __restrict__ x,
                                                  const float* __restrict__ bias,
                                                  float* __restrict__ out) {
    __shared__ __align__(16) float su[NDIM / SPLIT];
    __shared__ __align__(16) float sv[NDIM];
    const int t = threadIdx.x;
    const int b = blockIdx.x >> 3;
    const int s = blockIdx.x & (SPLIT - 1);

    sv[t] = g_v[t];
    if (t < NDIM / SPLIT) su[t] = g_u[s * (NDIM / SPLIT) + t];
    __syncthreads();

    const float4* __restrict__ xr = reinterpret_cast<const float4*>(
        x + (size_t)b * NDIM * NDIM + (size_t)s * (NDIM * NDIM / SPLIT));

    const int l  = (4 * t) & 511;
    const int k0 = (4 * t) >> 9;           // 0..3 within this chunk's rows
    const float4 v4 = *reinterpret_cast<const float4*>(&sv[l]);

    double acc = 0.0;
#pragma unroll
    for (int i = 0; i < ITERS; ++i) {
        const float4 xx = __ldcs(&xr[t + 512 * i]);
        const float uk = su[k0 + 4 * i];
        float d = xx.x * v4.x;
        d = fmaf(xx.y, v4.y, d);
        d = fmaf(xx.z, v4.z, d);
        d = fmaf(xx.w, v4.w, d);
        acc += (double)(uk * d);
    }

#pragma unroll
    for (int o = 16; o; o >>= 1)
        acc += __shfl_down_sync(0xffffffffu, acc, o);

    __shared__ double wsum[16];
    if ((t & 31) == 0) wsum[t >> 5] = acc;
    __syncthreads();
    if (t == 0) {
        double v = 0.0;
#pragma unroll
        for (int w = 0; w < 16; ++w) v += wsum[w];
        g_part[blockIdx.x] = v;
        __threadfence();
        const int old = atomicAdd(&g_cnt[b], 1);
        if (old == SPLIT - 1) {
            double sum = 0.0;
#pragma unroll
            for (int i = 0; i < SPLIT; ++i) sum += g_part[b * SPLIT + i];
            const float val = (float)sum + bias[0];
            out[b] = 1.0f / (1.0f + expf(-val));
            g_cnt[b] = 0;                  // reset for next graph replay
        }
    }
}

extern "C" void kernel_launch(void* const* d_in, const int* in_sizes, int n_in,
                              void* d_out, int out_size) {
    const float* x    = (const float*)d_in[0];
    const float* wh   = (const float*)d_in[1];
    const float* wv   = (const float*)d_in[2];
    const float* bias = (const float*)d_in[3];
    float* out = (float*)d_out;

    proj_kernel<<<NDIM, 256>>>(wh, wv);
    dot_kernel<<<BATCH * SPLIT, 512>>>(x, bias, out);
}